// round 8
// baseline (speedup 1.0000x reference)
#include <cuda_runtime.h>
#include <cuda_fp16.h>
#include <cstdint>

// ---------------- problem constants (fixed by the reference) ----------------
#define EMBD   256
#define HIDDEN 256
#define HNUM   8
#define CHD    32
#define BATCH  8
#define NQ     1024
#define ITOT   21760           // 128^2 + 64^2 + 32^2 + 16^2
#define QPW    384             // H*L*P*3
#define GK     256             // K for every GEMM
#define BNH    (BATCH * NQ * HNUM)   // 65536

// ---------------- scratch (no allocations allowed) ----------------
__device__ __half  g_img_p[BATCH * ITOT * HIDDEN];   // projected pyramid, fp16 (~89 MB)
__device__ __half  g_Wt1[HIDDEN * GK];               // W_img^T [N,K] fp16
__device__ __half  g_Wt2[QPW * GK];                  // W_q^T   [N,K] fp16
__device__ __half  g_Wt3[EMBD * GK];                 // W_out^T [N,K] fp16
__device__ float   g_qp[BATCH * NQ * QPW];           // query projection
__device__ float4  g_sw[BNH * 16];                   // 4 corner weights (x attn)
__device__ int4    g_si[BNH * 16];                   // 4 corner indices (x HIDDEN)
__device__ float   g_hidden[BATCH * NQ * HIDDEN];    // sampled context

__constant__ int c_sh[4]    = {128, 64, 32, 16};
__constant__ int c_start[4] = {0, 16384, 20480, 21504};

// ---------------- helpers ----------------
__device__ __forceinline__ void cp16(uint32_t dst, const void* src) {
    asm volatile("cp.async.cg.shared.global [%0], [%1], 16;" :: "r"(dst), "l"(src));
}
__device__ __forceinline__ uint32_t smem_u32(const void* p) {
    uint32_t a;
    asm("{ .reg .u64 t; cvta.to.shared.u64 t, %1; cvt.u32.u64 %0, t; }" : "=r"(a) : "l"(p));
    return a;
}
__device__ __forceinline__ uint32_t pack_h2(float lo, float hi) {
    uint32_t r;
    asm("cvt.rn.f16x2.f32 %0, %1, %2;" : "=r"(r) : "f"(hi), "f"(lo));
    return r;
}

// ============ GEMM1 hybrid: tensor-pipe blocks + FFMA-pipe blocks ============
// C_fp16[M,256] = A_fp32[M,256] @ W[256,256] + bias.
// blockIdx.y % FF_MOD == FF_MOD-1  -> FFMA personality (fp32 SGEMM, idle fma pipe)
// otherwise                        -> mma.sync personality (tensor pipe, f32 accum)
// The two personalities co-reside per SM, using disjoint execution pipes.

#define APITCH  24                 // halves per A/B row (16 used + 8 pad)
#define STG_H   (128 * APITCH)     // halves per stage per tile
#define NST     3
#define NKT16   (GK / 16)          // 16
#define FF_MOD  5                  // 1-in-5 slabs on the FFMA pipe (~20%)

__global__ __launch_bounds__(256) void gemm1_hybrid(
    const float* __restrict__ A, const __half* __restrict__ Wt,
    const float* __restrict__ W, const float* __restrict__ bias,
    __half* __restrict__ C)
{
    __shared__ union {
        struct { __half a[NST][STG_H]; __half b[NST][STG_H]; } t;   // 36 KB
        struct { float As[8][128]; float Bs[8][128]; } f;           // 8 KB
    } sm;

    const int tid = threadIdx.x;
    const int wid = tid >> 5;
    const int lane = tid & 31;
    const int m0 = blockIdx.y * 128;
    const int n0 = blockIdx.x * 128;

    if (blockIdx.y % FF_MOD == FF_MOD - 1) {
        // ================= FFMA personality (fp32, exact) =================
        const int a_row = tid >> 1;
        const int a_col = (tid & 1) * 4;
        const int b_row = tid >> 5;
        const int b_col = (tid & 31) * 4;
        const int ty = tid >> 4;
        const int tx = tid & 15;
        const int row_base = ty * 8;
        const int col_base = tx * 8;

        const float* Aptr = A + (size_t)(m0 + a_row) * GK + a_col;
        const float* Wptr = W + (size_t)b_row * HIDDEN + n0 + b_col;

        float acc[8][8];
        #pragma unroll
        for (int i = 0; i < 8; i++)
            #pragma unroll
            for (int j = 0; j < 8; j++) acc[i][j] = 0.f;

        for (int kt = 0; kt < GK; kt += 8) {
            float4 av = *(const float4*)(Aptr + kt);
            float4 bv = *(const float4*)(Wptr + (size_t)kt * HIDDEN);

            __syncthreads();
            sm.f.As[a_col + 0][a_row] = av.x;
            sm.f.As[a_col + 1][a_row] = av.y;
            sm.f.As[a_col + 2][a_row] = av.z;
            sm.f.As[a_col + 3][a_row] = av.w;
            *(float4*)&sm.f.Bs[b_row][b_col] = bv;
            __syncthreads();

            #pragma unroll
            for (int k = 0; k < 8; k++) {
                float a[8], b[8];
                *(float4*)(a)     = *(const float4*)&sm.f.As[k][row_base];
                *(float4*)(a + 4) = *(const float4*)&sm.f.As[k][row_base + 4];
                *(float4*)(b)     = *(const float4*)&sm.f.Bs[k][col_base];
                *(float4*)(b + 4) = *(const float4*)&sm.f.Bs[k][col_base + 4];
                #pragma unroll
                for (int i = 0; i < 8; i++)
                    #pragma unroll
                    for (int j = 0; j < 8; j++)
                        acc[i][j] = fmaf(a[i], b[j], acc[i][j]);
            }
        }

        float bb[8];
        #pragma unroll
        for (int j = 0; j < 8; j++) bb[j] = bias[n0 + col_base + j];

        #pragma unroll
        for (int i = 0; i < 8; i++) {
            __half* crow = C + (size_t)(m0 + row_base + i) * HIDDEN + n0 + col_base;
            #pragma unroll
            for (int j = 0; j < 8; j += 2) {
                *(uint32_t*)(crow + j) = pack_h2(acc[i][j] + bb[j], acc[i][j + 1] + bb[j + 1]);
            }
        }
        return;
    }

    // ================= tensor personality (mma.sync, f32 accum) =================
    const int g = lane >> 2;
    const int tig = lane & 3;
    const int wm = (wid & 1) * 64;
    const int wn = (wid >> 1) * 32;

    const uint32_t lds_a_off = (uint32_t)((wm + (lane & 15)) * APITCH + (lane >> 4) * 8) * 2;

    uint32_t sbA[NST], sbB[NST];
    #pragma unroll
    for (int s = 0; s < NST; s++) {
        sbA[s] = smem_u32(&sm.t.a[s][0]);
        sbB[s] = smem_u32(&sm.t.b[s][0]);
    }

    const int arow = tid >> 1, aseg = tid & 1;
    const float* Ab = A + (size_t)(m0 + arow) * GK + aseg * 8;
    const __half* Bb = Wt + (size_t)(n0 + arow) * GK + aseg * 8;
    const uint32_t st_off = (uint32_t)(arow * APITCH + aseg * 8) * 2;

    float4 rA[2][2];
    auto ldgA = [&](int kt, int slot) {
        const float* p = Ab + kt * 16;
        rA[slot][0] = *(const float4*)p;
        rA[slot][1] = *(const float4*)(p + 4);
    };
    auto stsA = [&](int buf, int slot) {
        uint4 v;
        v.x = pack_h2(rA[slot][0].x, rA[slot][0].y);
        v.y = pack_h2(rA[slot][0].z, rA[slot][0].w);
        v.z = pack_h2(rA[slot][1].x, rA[slot][1].y);
        v.w = pack_h2(rA[slot][1].z, rA[slot][1].w);
        *(uint4*)((char*)&sm.t.a[buf][0] + st_off) = v;
    };
    auto cpB = [&](int buf, int kt) {
        cp16(sbB[buf] + st_off, Bb + kt * 16);
    };

    float acc[4][4][4];
    #pragma unroll
    for (int i = 0; i < 4; i++)
        #pragma unroll
        for (int j = 0; j < 4; j++)
            #pragma unroll
            for (int r = 0; r < 4; r++) acc[i][j][r] = 0.f;

    // prologue
    ldgA(0, 0); ldgA(1, 1);
    cpB(0, 0);  asm volatile("cp.async.commit_group;" ::: "memory");
    cpB(1, 1);  asm volatile("cp.async.commit_group;" ::: "memory");
    stsA(0, 0); ldgA(2, 0);

    int buf = 0;
    #pragma unroll 1
    for (int kt = 0; kt < NKT16; kt++) {
        if (kt < NKT16 - 1) {
            asm volatile("cp.async.wait_group 1;" ::: "memory");
        } else {
            asm volatile("cp.async.wait_group 0;" ::: "memory");
        }
        __syncthreads();

        if (kt + 2 < NKT16) {
            int nb = buf + 2; if (nb >= NST) nb -= NST;
            cpB(nb, kt + 2);
            asm volatile("cp.async.commit_group;" ::: "memory");
        }

        uint32_t a[4][4], b[4][2];
        #pragma unroll
        for (int mf = 0; mf < 4; mf++) {
            uint32_t addr = sbA[buf] + lds_a_off + (uint32_t)(mf * 16 * APITCH) * 2;
            asm volatile(
                "ldmatrix.sync.aligned.m8n8.x4.shared.b16 {%0,%1,%2,%3}, [%4];"
                : "=r"(a[mf][0]), "=r"(a[mf][1]), "=r"(a[mf][2]), "=r"(a[mf][3])
                : "r"(addr));
        }
        const __half* Bs = sm.t.b[buf];
        #pragma unroll
        for (int nf = 0; nf < 4; nf++) {
            int rb = wn + nf * 8 + g;
            b[nf][0] = *(const uint32_t*)&Bs[rb * APITCH + tig * 2];
            b[nf][1] = *(const uint32_t*)&Bs[rb * APITCH + tig * 2 + 8];
        }
        #pragma unroll
        for (int mf = 0; mf < 4; mf++)
            #pragma unroll
            for (int nf = 0; nf < 4; nf++) {
                asm volatile(
                    "mma.sync.aligned.m16n8k16.row.col.f32.f16.f16.f32 "
                    "{%0,%1,%2,%3}, {%4,%5,%6,%7}, {%8,%9}, {%0,%1,%2,%3};"
                    : "+f"(acc[mf][nf][0]), "+f"(acc[mf][nf][1]),
                      "+f"(acc[mf][nf][2]), "+f"(acc[mf][nf][3])
                    : "r"(a[mf][0]), "r"(a[mf][1]), "r"(a[mf][2]), "r"(a[mf][3]),
                      "r"(b[nf][0]), "r"(b[nf][1]));
            }

        if (kt + 1 < NKT16) {
            int nb = buf + 1; if (nb >= NST) nb -= NST;
            stsA(nb, (kt + 1) & 1);
        }
        if (kt + 3 < NKT16) ldgA(kt + 3, (kt + 3) & 1);

        if (++buf == NST) buf = 0;
    }

    #pragma unroll
    for (int nf = 0; nf < 4; nf++) {
        const int col = n0 + wn + nf * 8 + tig * 2;
        const float2 bb = *(const float2*)(bias + col);
        #pragma unroll
        for (int mf = 0; mf < 4; mf++) {
            const int row = m0 + wm + mf * 16 + g;
            uint32_t h0 = pack_h2(acc[mf][nf][0] + bb.x, acc[mf][nf][1] + bb.y);
            uint32_t h1 = pack_h2(acc[mf][nf][2] + bb.x, acc[mf][nf][3] + bb.y);
            *(uint32_t*)(C + (size_t)row * HIDDEN + col) = h0;
            *(uint32_t*)(C + (size_t)(row + 8) * HIDDEN + col) = h1;
        }
    }
}

// =============== fp16 mma GEMM, f32 accum (GEMM2/3) ===============
#define ROWPAD  20
#define BPITCH  24
#define A_STG   (128 * ROWPAD)
#define B_STG   (64 * BPITCH)
#define NSTAGE  3
#define NKT     (GK / 16)

__global__ __launch_bounds__(256) void hgemm(
    const float* __restrict__ A, const __half* __restrict__ Wt,
    const float* __restrict__ bias, float* __restrict__ C,
    int M, int N)
{
    __shared__ float  sA[NSTAGE][A_STG];
    __shared__ __half sB[NSTAGE][B_STG];

    const int tid = threadIdx.x;
    const int wid = tid >> 5;
    const int lane = tid & 31;
    const int g = lane >> 2;
    const int tig = lane & 3;
    const int m0 = blockIdx.y * 128;
    const int n0 = blockIdx.x * 64;
    const int wm = (wid & 3) * 32;
    const int wn = (wid >> 2) * 32;

    float acc[2][4][4];
    #pragma unroll
    for (int i = 0; i < 2; i++)
        #pragma unroll
        for (int j = 0; j < 4; j++)
            #pragma unroll
            for (int r = 0; r < 4; r++) acc[i][j][r] = 0.f;

    uint32_t sbA[NSTAGE], sbB[NSTAGE];
    #pragma unroll
    for (int s = 0; s < NSTAGE; s++) {
        sbA[s] = smem_u32(&sA[s][0]);
        sbB[s] = smem_u32(&sB[s][0]);
    }

    auto load_stage = [&](int s, int kt) {
        #pragma unroll
        for (int i = 0; i < 2; i++) {
            int id = tid + i * 256;
            int row = id >> 2, c = id & 3;
            cp16(sbA[s] + (uint32_t)(row * ROWPAD + c * 4) * 4,
                 A + (size_t)(m0 + row) * GK + kt * 16 + c * 4);
        }
        if (tid < 128) {
            int row = tid >> 1, c = tid & 1;
            cp16(sbB[s] + (uint32_t)(row * BPITCH + c * 8) * 2,
                 Wt + (size_t)(n0 + row) * GK + kt * 16 + c * 8);
        }
    };

    load_stage(0, 0);
    asm volatile("cp.async.commit_group;" ::: "memory");
    load_stage(1, 1);
    asm volatile("cp.async.commit_group;" ::: "memory");

    #pragma unroll 1
    for (int kt = 0; kt < NKT; kt++) {
        if (kt < NKT - 1) {
            asm volatile("cp.async.wait_group 1;" ::: "memory");
        } else {
            asm volatile("cp.async.wait_group 0;" ::: "memory");
        }
        __syncthreads();

        if (kt + 2 < NKT) {
            load_stage((kt + 2) % NSTAGE, kt + 2);
            asm volatile("cp.async.commit_group;" ::: "memory");
        }

        const float*  As = sA[kt % NSTAGE];
        const __half* Bs = sB[kt % NSTAGE];

        uint32_t a[2][4], b[4][2];
        #pragma unroll
        for (int mf = 0; mf < 2; mf++) {
            int r = wm + mf * 16 + g;
            a[mf][0] = pack_h2(As[r * ROWPAD + tig * 2], As[r * ROWPAD + tig * 2 + 1]);
            a[mf][1] = pack_h2(As[(r + 8) * ROWPAD + tig * 2], As[(r + 8) * ROWPAD + tig * 2 + 1]);
            a[mf][2] = pack_h2(As[r * ROWPAD + tig * 2 + 8], As[r * ROWPAD + tig * 2 + 9]);
            a[mf][3] = pack_h2(As[(r + 8) * ROWPAD + tig * 2 + 8], As[(r + 8) * ROWPAD + tig * 2 + 9]);
        }
        #pragma unroll
        for (int nf = 0; nf < 4; nf++) {
            int rb = wn + nf * 8 + g;
            b[nf][0] = *(const uint32_t*)&Bs[rb * BPITCH + tig * 2];
            b[nf][1] = *(const uint32_t*)&Bs[rb * BPITCH + tig * 2 + 8];
        }
        #pragma unroll
        for (int mf = 0; mf < 2; mf++)
            #pragma unroll
            for (int nf = 0; nf < 4; nf++) {
                asm volatile(
                    "mma.sync.aligned.m16n8k16.row.col.f32.f16.f16.f32 "
                    "{%0,%1,%2,%3}, {%4,%5,%6,%7}, {%8,%9}, {%0,%1,%2,%3};"
                    : "+f"(acc[mf][nf][0]), "+f"(acc[mf][nf][1]),
                      "+f"(acc[mf][nf][2]), "+f"(acc[mf][nf][3])
                    : "r"(a[mf][0]), "r"(a[mf][1]), "r"(a[mf][2]), "r"(a[mf][3]),
                      "r"(b[nf][0]), "r"(b[nf][1]));
            }
    }

    #pragma unroll
    for (int nf = 0; nf < 4; nf++) {
        const int col = n0 + wn + nf * 8 + tig * 2;
        const float2 bb = *(const float2*)(bias + col);
        #pragma unroll
        for (int mf = 0; mf < 2; mf++) {
            const int row = m0 + wm + mf * 16 + g;
            float2 v0 = make_float2(acc[mf][nf][0] + bb.x, acc[mf][nf][1] + bb.y);
            float2 v1 = make_float2(acc[mf][nf][2] + bb.x, acc[mf][nf][3] + bb.y);
            *(float2*)(C + (size_t)row * N + col) = v0;
            *(float2*)(C + (size_t)(row + 8) * N + col) = v1;
        }
    }
}

// W [K=256, N] fp32 row-major  ->  Wt [N, K] fp16 row-major
__global__ void pack_wt(const float* __restrict__ W, __half* __restrict__ Wt, int N) {
    __shared__ float t[32][33];
    int bx = blockIdx.x * 32;
    int by = blockIdx.y * 32;
    int x = threadIdx.x, y = threadIdx.y;
    #pragma unroll
    for (int i = 0; i < 32; i += 8)
        t[y + i][x] = W[(size_t)(by + y + i) * N + bx + x];
    __syncthreads();
    #pragma unroll
    for (int i = 0; i < 32; i += 8)
        Wt[(size_t)(bx + y + i) * GK + by + x] = __float2half_rn(t[x][y + i]);
}

// ---------------- prep: softmax + bilinear weights + clamped corner indices ----------------
__global__ void msda_prep(const float* __restrict__ qp,
                          const float* __restrict__ refpts,
                          float4* __restrict__ sw,
                          int4* __restrict__ si)
{
    int t = blockIdx.x * blockDim.x + threadIdx.x;
    if (t >= BNH) return;
    int bn = t / HNUM;

    const float* q = qp + (size_t)t * 48;

    float lg[16];
    float mx = -1e30f;
    #pragma unroll
    for (int s = 0; s < 16; s++) { lg[s] = q[s * 3 + 2]; mx = fmaxf(mx, lg[s]); }
    float sum = 0.f;
    #pragma unroll
    for (int s = 0; s < 16; s++) { lg[s] = expf(lg[s] - mx); sum += lg[s]; }
    float inv = 1.0f / sum;

    float rx = refpts[bn * 2 + 0];
    float ry = refpts[bn * 2 + 1];

    #pragma unroll
    for (int s = 0; s < 16; s++) {
        int l = s >> 2;
        int sh = c_sh[l];
        float fs = (float)sh;
        int st = c_start[l];
        float aw = lg[s] * inv;

        float px = rx + q[s * 3 + 0] / fs;
        float py = ry + q[s * 3 + 1] / fs;
        float x = px * fs - 0.5f;
        float y = py * fs - 0.5f;
        float x0f = floorf(x), y0f = floorf(y);
        int x0 = (int)x0f, y0 = (int)y0f;
        float wx = x - x0f, wy = y - y0f;

        float w00 = (1.f - wx) * (1.f - wy) * aw;
        float w10 = wx * (1.f - wy) * aw;
        float w01 = (1.f - wx) * wy * aw;
        float w11 = wx * wy * aw;

        bool vx0 = (x0 >= 0) & (x0 < sh);
        bool vx1 = (x0 + 1 >= 0) & (x0 + 1 < sh);
        bool vy0 = (y0 >= 0) & (y0 < sh);
        bool vy1 = (y0 + 1 >= 0) & (y0 + 1 < sh);

        int xc0 = min(max(x0, 0), sh - 1);
        int xc1 = min(max(x0 + 1, 0), sh - 1);
        int yc0 = min(max(y0, 0), sh - 1);
        int yc1 = min(max(y0 + 1, 0), sh - 1);

        float4 w4;
        w4.x = (vx0 & vy0) ? w00 : 0.f;
        w4.y = (vx1 & vy0) ? w10 : 0.f;
        w4.z = (vx0 & vy1) ? w01 : 0.f;
        w4.w = (vx1 & vy1) ? w11 : 0.f;

        int4 i4;
        i4.x = (st + yc0 * sh + xc0) * HIDDEN;
        i4.y = (st + yc0 * sh + xc1) * HIDDEN;
        i4.z = (st + yc1 * sh + xc0) * HIDDEN;
        i4.w = (st + yc1 * sh + xc1) * HIDDEN;

        sw[(size_t)t * 16 + s] = w4;
        si[(size_t)t * 16 + s] = i4;
    }
}

// ---------------- gather: one warp covers TWO heads (half2 channels) ----------------
__global__ __launch_bounds__(256) void msda_sample2(
    const __half* __restrict__ img_p,
    const float4* __restrict__ sw,
    const int4* __restrict__ si,
    float* __restrict__ out)
{
    int w2 = blockIdx.x * 8 + (threadIdx.x >> 5);   // head-pair id, [0, BNH/2)
    int lane = threadIdx.x & 31;
    int hp = lane >> 4;                              // 0 or 1
    int ch2 = lane & 15;                             // half2 channel index

    int t = w2 * 2 + hp;                             // (b*NQ+n)*HNUM + h
    int h = t & (HNUM - 1);
    int b = t / (NQ * HNUM);

    const __half* base = img_p + (size_t)b * ITOT * HIDDEN + h * CHD + ch2 * 2;
    const float4* wp = sw + (size_t)t * 16;
    const int4*   ip = si + (size_t)t * 16;

    float2 acc = make_float2(0.f, 0.f);
    #pragma unroll
    for (int s = 0; s < 16; s++) {
        float4 wt = __ldg(wp + s);
        int4   ix = __ldg(ip + s);
        float2 v0 = __half22float2(*(const __half2*)(base + ix.x));
        float2 v1 = __half22float2(*(const __half2*)(base + ix.y));
        float2 v2 = __half22float2(*(const __half2*)(base + ix.z));
        float2 v3 = __half22float2(*(const __half2*)(base + ix.w));
        acc.x += wt.x * v0.x + wt.y * v1.x + wt.z * v2.x + wt.w * v3.x;
        acc.y += wt.x * v0.y + wt.y * v1.y + wt.z * v2.y + wt.w * v3.y;
    }
    *(float2*)(out + (size_t)t * CHD + ch2 * 2) = acc;
}

// ---------------- launch ----------------
extern "C" void kernel_launch(void* const* d_in, const int* in_sizes, int n_in,
                              void* d_out, int out_size)
{
    const float* img     = (const float*)d_in[0];
    const float* queries = (const float*)d_in[2];
    const float* refpts  = (const float*)d_in[3];
    const float* W_img   = (const float*)d_in[4];
    const float* b_img   = (const float*)d_in[5];
    const float* W_q     = (const float*)d_in[6];
    const float* b_q     = (const float*)d_in[7];
    const float* W_out   = (const float*)d_in[8];
    const float* b_out   = (const float*)d_in[9];
    float* out = (float*)d_out;

    float *qp, *hidden;
    __half *img_p, *Wt1, *Wt2, *Wt3;
    float4* sw;
    int4* si;
    cudaGetSymbolAddress((void**)&img_p,  g_img_p);
    cudaGetSymbolAddress((void**)&qp,     g_qp);
    cudaGetSymbolAddress((void**)&sw,     g_sw);
    cudaGetSymbolAddress((void**)&si,     g_si);
    cudaGetSymbolAddress((void**)&hidden, g_hidden);
    cudaGetSymbolAddress((void**)&Wt1,    g_Wt1);
    cudaGetSymbolAddress((void**)&Wt2,    g_Wt2);
    cudaGetSymbolAddress((void**)&Wt3,    g_Wt3);

    // 0) pack weights
    {
        dim3 blk(32, 8);
        pack_wt<<<dim3(HIDDEN / 32, GK / 32), blk>>>(W_img, Wt1, HIDDEN);
        pack_wt<<<dim3(QPW    / 32, GK / 32), blk>>>(W_q,   Wt2, QPW);
        pack_wt<<<dim3(EMBD   / 32, GK / 32), blk>>>(W_out, Wt3, EMBD);
    }
    // 1) img projection -> fp16 img_p (hybrid: tensor + FFMA pipes concurrently)
    gemm1_hybrid<<<dim3(HIDDEN / 128, (BATCH * ITOT) / 128), 256>>>(
        img, Wt1, W_img, b_img, img_p);
    // 2) query projection (fp32 out)
    hgemm<<<dim3(QPW / 64, (BATCH * NQ) / 128), 256>>>(
        queries, Wt2, b_q, qp, BATCH * NQ, QPW);
    // 3) softmax + weights/indices precompute
    msda_prep<<<(BNH + 127) / 128, 128>>>(qp, refpts, sw, si);
    // 4) gather + attention reduce (2 heads per warp)
    msda_sample2<<<(BNH / 2) / 8, 256>>>(img_p, sw, si, hidden);
    // 5) output projection
    hgemm<<<dim3(HIDDEN / 64, (BATCH * NQ) / 128), 256>>>(
        hidden, Wt3, b_out, out, BATCH * NQ, HIDDEN);
}

// round 9
// speedup vs baseline: 1.2266x; 1.2266x over previous
#include <cuda_runtime.h>
#include <cuda_fp16.h>
#include <cstdint>

// ---------------- problem constants (fixed by the reference) ----------------
#define EMBD   256
#define HIDDEN 256
#define HNUM   8
#define CHD    32
#define BATCH  8
#define NQ     1024
#define ITOT   21760           // 128^2 + 64^2 + 32^2 + 16^2
#define QPW    384             // H*L*P*3
#define GK     256             // K for every GEMM
#define BNH    (BATCH * NQ * HNUM)   // 65536

// ---------------- scratch (no allocations allowed) ----------------
__device__ __half  g_img_p[BATCH * ITOT * HIDDEN];   // projected pyramid, fp16 (~89 MB)
__device__ __half  g_Wt1[HIDDEN * GK];               // W_img^T [N,K] fp16
__device__ __half  g_Wt2[QPW * GK];                  // W_q^T   [N,K] fp16
__device__ __half  g_Wt3[EMBD * GK];                 // W_out^T [N,K] fp16
__device__ float   g_qp[BATCH * NQ * QPW];           // query projection
__device__ float4  g_sw[BNH * 16];                   // 4 corner weights (x attn)
__device__ int4    g_si[BNH * 16];                   // 4 corner indices (x HIDDEN)
__device__ float   g_hidden[BATCH * NQ * HIDDEN];    // sampled context
__device__ unsigned g_ctr[12];                       // dependency counters

#define CTR_G2   8
#define CTR_PREP 9
#define CTR_SMP  10

__constant__ int c_sh[4]    = {128, 64, 32, 16};
__constant__ int c_start[4] = {0, 16384, 20480, 21504};

// ---------------- helpers ----------------
__device__ __forceinline__ void cp16(uint32_t dst, const void* src) {
    asm volatile("cp.async.cg.shared.global [%0], [%1], 16;" :: "r"(dst), "l"(src));
}
__device__ __forceinline__ uint32_t smem_u32(const void* p) {
    uint32_t a;
    asm("{ .reg .u64 t; cvta.to.shared.u64 t, %1; cvt.u32.u64 %0, t; }" : "=r"(a) : "l"(p));
    return a;
}
__device__ __forceinline__ uint32_t pack_h2(float lo, float hi) {
    uint32_t r;
    asm("cvt.rn.f16x2.f32 %0, %1, %2;" : "=r"(r) : "f"(hi), "f"(lo));
    return r;
}

// release: all writes of this block visible, then bump counter
__device__ __forceinline__ void signal_ctr(int idx) {
    __threadfence();
    __syncthreads();
    if (threadIdx.x == 0) atomicAdd(&g_ctr[idx], 1u);
}
// acquire: wait for counters, then fence (gpu-scope fence invalidates L1)
__device__ __forceinline__ void wait2(int i0, unsigned t0, int i1, unsigned t1) {
    if (threadIdx.x == 0) {
        volatile unsigned* c = g_ctr;
        while (c[i0] < t0) __nanosleep(128);
        if (i1 >= 0) while (c[i1] < t1) __nanosleep(128);
    }
    __syncthreads();
    __threadfence();
}

// ================= personality: GEMM1 tile (fp16 MMA, f32 acc, ldmatrix) =================
#define APITCH  24
#define STG_H   (128 * APITCH)
#define NST     3
#define NKT16   (GK / 16)

__device__ void gemm1_tile(const float* __restrict__ Arows, const __half* __restrict__ Wt,
                           const float* __restrict__ bias, __half* __restrict__ Crows,
                           int n0, char* dynsm)
{
    __half* sA16 = (__half*)dynsm;                 // NST * STG_H halves
    __half* sB16 = sA16 + NST * STG_H;

    const int tid = threadIdx.x;
    const int wid = tid >> 5;
    const int lane = tid & 31;
    const int g = lane >> 2;
    const int tig = lane & 3;
    const int wm = (wid & 1) * 64;
    const int wn = (wid >> 1) * 32;

    const uint32_t lds_a_off = (uint32_t)((wm + (lane & 15)) * APITCH + (lane >> 4) * 8) * 2;

    uint32_t sbA[NST], sbB[NST];
    #pragma unroll
    for (int s = 0; s < NST; s++) {
        sbA[s] = smem_u32(sA16 + s * STG_H);
        sbB[s] = smem_u32(sB16 + s * STG_H);
    }

    const int arow = tid >> 1, aseg = tid & 1;
    const float* Ab = Arows + (size_t)arow * GK + aseg * 8;
    const __half* Bb = Wt + (size_t)(n0 + arow) * GK + aseg * 8;
    const uint32_t st_off = (uint32_t)(arow * APITCH + aseg * 8) * 2;

    float4 rA[2][2];
    auto ldgA = [&](int kt, int slot) {
        const float* p = Ab + kt * 16;
        rA[slot][0] = *(const float4*)p;
        rA[slot][1] = *(const float4*)(p + 4);
    };
    auto stsA = [&](int buf, int slot) {
        uint4 v;
        v.x = pack_h2(rA[slot][0].x, rA[slot][0].y);
        v.y = pack_h2(rA[slot][0].z, rA[slot][0].w);
        v.z = pack_h2(rA[slot][1].x, rA[slot][1].y);
        v.w = pack_h2(rA[slot][1].z, rA[slot][1].w);
        *(uint4*)((char*)(sA16 + buf * STG_H) + st_off) = v;
    };
    auto cpB = [&](int buf, int kt) {
        cp16(sbB[buf] + st_off, Bb + kt * 16);
    };

    float acc[4][4][4];
    #pragma unroll
    for (int i = 0; i < 4; i++)
        #pragma unroll
        for (int j = 0; j < 4; j++)
            #pragma unroll
            for (int r = 0; r < 4; r++) acc[i][j][r] = 0.f;

    ldgA(0, 0); ldgA(1, 1);
    cpB(0, 0);  asm volatile("cp.async.commit_group;" ::: "memory");
    cpB(1, 1);  asm volatile("cp.async.commit_group;" ::: "memory");
    stsA(0, 0); ldgA(2, 0);

    int buf = 0;
    #pragma unroll 1
    for (int kt = 0; kt < NKT16; kt++) {
        if (kt < NKT16 - 1) {
            asm volatile("cp.async.wait_group 1;" ::: "memory");
        } else {
            asm volatile("cp.async.wait_group 0;" ::: "memory");
        }
        __syncthreads();

        if (kt + 2 < NKT16) {
            int nb = buf + 2; if (nb >= NST) nb -= NST;
            cpB(nb, kt + 2);
            asm volatile("cp.async.commit_group;" ::: "memory");
        }

        uint32_t a[4][4], b[4][2];
        #pragma unroll
        for (int mf = 0; mf < 4; mf++) {
            uint32_t addr = sbA[buf] + lds_a_off + (uint32_t)(mf * 16 * APITCH) * 2;
            asm volatile(
                "ldmatrix.sync.aligned.m8n8.x4.shared.b16 {%0,%1,%2,%3}, [%4];"
                : "=r"(a[mf][0]), "=r"(a[mf][1]), "=r"(a[mf][2]), "=r"(a[mf][3])
                : "r"(addr));
        }
        const __half* Bs = sB16 + buf * STG_H;
        #pragma unroll
        for (int nf = 0; nf < 4; nf++) {
            int rb = wn + nf * 8 + g;
            b[nf][0] = *(const uint32_t*)&Bs[rb * APITCH + tig * 2];
            b[nf][1] = *(const uint32_t*)&Bs[rb * APITCH + tig * 2 + 8];
        }
        #pragma unroll
        for (int mf = 0; mf < 4; mf++)
            #pragma unroll
            for (int nf = 0; nf < 4; nf++) {
                asm volatile(
                    "mma.sync.aligned.m16n8k16.row.col.f32.f16.f16.f32 "
                    "{%0,%1,%2,%3}, {%4,%5,%6,%7}, {%8,%9}, {%0,%1,%2,%3};"
                    : "+f"(acc[mf][nf][0]), "+f"(acc[mf][nf][1]),
                      "+f"(acc[mf][nf][2]), "+f"(acc[mf][nf][3])
                    : "r"(a[mf][0]), "r"(a[mf][1]), "r"(a[mf][2]), "r"(a[mf][3]),
                      "r"(b[nf][0]), "r"(b[nf][1]));
            }

        if (kt + 1 < NKT16) {
            int nb = buf + 1; if (nb >= NST) nb -= NST;
            stsA(nb, (kt + 1) & 1);
        }
        if (kt + 3 < NKT16) ldgA(kt + 3, (kt + 3) & 1);

        if (++buf == NST) buf = 0;
    }

    #pragma unroll
    for (int nf = 0; nf < 4; nf++) {
        const int col = n0 + wn + nf * 8 + tig * 2;
        const float2 bb = *(const float2*)(bias + col);
        #pragma unroll
        for (int mf = 0; mf < 4; mf++) {
            const int row = wm + mf * 16 + g;
            uint32_t h0 = pack_h2(acc[mf][nf][0] + bb.x, acc[mf][nf][1] + bb.y);
            uint32_t h1 = pack_h2(acc[mf][nf][2] + bb.x, acc[mf][nf][3] + bb.y);
            *(uint32_t*)(Crows + (size_t)row * HIDDEN + col) = h0;
            *(uint32_t*)(Crows + (size_t)(row + 8) * HIDDEN + col) = h1;
        }
    }
}

// ================= personality: fp32-out fp16 MMA GEMM (GEMM2 / GEMM3) =================
#define ROWPAD  20
#define BPITCH  24
#define A_STG   (128 * ROWPAD)
#define B_STG   (64 * BPITCH)
#define NSTAGE  3
#define NKT     (GK / 16)

__device__ void hgemm_tile(const float* __restrict__ A, const __half* __restrict__ Wt,
                           const float* __restrict__ bias, float* __restrict__ C,
                           int N, int m0, int n0, char* dynsm)
{
    float*  sA = (float*)dynsm;                          // NSTAGE * A_STG floats
    __half* sB = (__half*)(dynsm + NSTAGE * A_STG * 4);  // NSTAGE * B_STG halves

    const int tid = threadIdx.x;
    const int wid = tid >> 5;
    const int lane = tid & 31;
    const int g = lane >> 2;
    const int tig = lane & 3;
    const int wm = (wid & 3) * 32;
    const int wn = (wid >> 2) * 32;

    float acc[2][4][4];
    #pragma unroll
    for (int i = 0; i < 2; i++)
        #pragma unroll
        for (int j = 0; j < 4; j++)
            #pragma unroll
            for (int r = 0; r < 4; r++) acc[i][j][r] = 0.f;

    uint32_t sbA[NSTAGE], sbB[NSTAGE];
    #pragma unroll
    for (int s = 0; s < NSTAGE; s++) {
        sbA[s] = smem_u32(sA + s * A_STG);
        sbB[s] = smem_u32(sB + s * B_STG);
    }

    auto load_stage = [&](int s, int kt) {
        #pragma unroll
        for (int i = 0; i < 2; i++) {
            int id = tid + i * 256;
            int row = id >> 2, c = id & 3;
            cp16(sbA[s] + (uint32_t)(row * ROWPAD + c * 4) * 4,
                 A + (size_t)(m0 + row) * GK + kt * 16 + c * 4);
        }
        if (tid < 128) {
            int row = tid >> 1, c = tid & 1;
            cp16(sbB[s] + (uint32_t)(row * BPITCH + c * 8) * 2,
                 Wt + (size_t)(n0 + row) * GK + kt * 16 + c * 8);
        }
    };

    load_stage(0, 0);
    asm volatile("cp.async.commit_group;" ::: "memory");
    load_stage(1, 1);
    asm volatile("cp.async.commit_group;" ::: "memory");

    #pragma unroll 1
    for (int kt = 0; kt < NKT; kt++) {
        if (kt < NKT - 1) {
            asm volatile("cp.async.wait_group 1;" ::: "memory");
        } else {
            asm volatile("cp.async.wait_group 0;" ::: "memory");
        }
        __syncthreads();

        if (kt + 2 < NKT) {
            load_stage((kt + 2) % NSTAGE, kt + 2);
            asm volatile("cp.async.commit_group;" ::: "memory");
        }

        const float*  As = sA + (kt % NSTAGE) * A_STG;
        const __half* Bs = sB + (kt % NSTAGE) * B_STG;

        uint32_t a[2][4], b[4][2];
        #pragma unroll
        for (int mf = 0; mf < 2; mf++) {
            int r = wm + mf * 16 + g;
            a[mf][0] = pack_h2(As[r * ROWPAD + tig * 2], As[r * ROWPAD + tig * 2 + 1]);
            a[mf][1] = pack_h2(As[(r + 8) * ROWPAD + tig * 2], As[(r + 8) * ROWPAD + tig * 2 + 1]);
            a[mf][2] = pack_h2(As[r * ROWPAD + tig * 2 + 8], As[r * ROWPAD + tig * 2 + 9]);
            a[mf][3] = pack_h2(As[(r + 8) * ROWPAD + tig * 2 + 8], As[(r + 8) * ROWPAD + tig * 2 + 9]);
        }
        #pragma unroll
        for (int nf = 0; nf < 4; nf++) {
            int rb = wn + nf * 8 + g;
            b[nf][0] = *(const uint32_t*)&Bs[rb * BPITCH + tig * 2];
            b[nf][1] = *(const uint32_t*)&Bs[rb * BPITCH + tig * 2 + 8];
        }
        #pragma unroll
        for (int mf = 0; mf < 2; mf++)
            #pragma unroll
            for (int nf = 0; nf < 4; nf++) {
                asm volatile(
                    "mma.sync.aligned.m16n8k16.row.col.f32.f16.f16.f32 "
                    "{%0,%1,%2,%3}, {%4,%5,%6,%7}, {%8,%9}, {%0,%1,%2,%3};"
                    : "+f"(acc[mf][nf][0]), "+f"(acc[mf][nf][1]),
                      "+f"(acc[mf][nf][2]), "+f"(acc[mf][nf][3])
                    : "r"(a[mf][0]), "r"(a[mf][1]), "r"(a[mf][2]), "r"(a[mf][3]),
                      "r"(b[nf][0]), "r"(b[nf][1]));
            }
    }

    #pragma unroll
    for (int nf = 0; nf < 4; nf++) {
        const int col = n0 + wn + nf * 8 + tig * 2;
        const float2 bb = *(const float2*)(bias + col);
        #pragma unroll
        for (int mf = 0; mf < 2; mf++) {
            const int row = m0 + wm + mf * 16 + g;
            float2 v0 = make_float2(acc[mf][nf][0] + bb.x, acc[mf][nf][1] + bb.y);
            float2 v1 = make_float2(acc[mf][nf][2] + bb.x, acc[mf][nf][3] + bb.y);
            *(float2*)(C + (size_t)row * N + col) = v0;
            *(float2*)(C + (size_t)(row + 8) * N + col) = v1;
        }
    }
}

// ================= personality: prep (softmax + weights/indices) =================
__device__ void prep_body(int t, const float* __restrict__ qp,
                          const float* __restrict__ refpts)
{
    int bn = t / HNUM;
    const float* q = qp + (size_t)t * 48;

    float lg[16];
    float mx = -1e30f;
    #pragma unroll
    for (int s = 0; s < 16; s++) { lg[s] = q[s * 3 + 2]; mx = fmaxf(mx, lg[s]); }
    float sum = 0.f;
    #pragma unroll
    for (int s = 0; s < 16; s++) { lg[s] = expf(lg[s] - mx); sum += lg[s]; }
    float inv = 1.0f / sum;

    float rx = refpts[bn * 2 + 0];
    float ry = refpts[bn * 2 + 1];

    #pragma unroll
    for (int s = 0; s < 16; s++) {
        int l = s >> 2;
        int sh = c_sh[l];
        float fs = (float)sh;
        int st = c_start[l];
        float aw = lg[s] * inv;

        float px = rx + q[s * 3 + 0] / fs;
        float py = ry + q[s * 3 + 1] / fs;
        float x = px * fs - 0.5f;
        float y = py * fs - 0.5f;
        float x0f = floorf(x), y0f = floorf(y);
        int x0 = (int)x0f, y0 = (int)y0f;
        float wx = x - x0f, wy = y - y0f;

        float w00 = (1.f - wx) * (1.f - wy) * aw;
        float w10 = wx * (1.f - wy) * aw;
        float w01 = (1.f - wx) * wy * aw;
        float w11 = wx * wy * aw;

        bool vx0 = (x0 >= 0) & (x0 < sh);
        bool vx1 = (x0 + 1 >= 0) & (x0 + 1 < sh);
        bool vy0 = (y0 >= 0) & (y0 < sh);
        bool vy1 = (y0 + 1 >= 0) & (y0 + 1 < sh);

        int xc0 = min(max(x0, 0), sh - 1);
        int xc1 = min(max(x0 + 1, 0), sh - 1);
        int yc0 = min(max(y0, 0), sh - 1);
        int yc1 = min(max(y0 + 1, 0), sh - 1);

        float4 w4;
        w4.x = (vx0 & vy0) ? w00 : 0.f;
        w4.y = (vx1 & vy0) ? w10 : 0.f;
        w4.z = (vx0 & vy1) ? w01 : 0.f;
        w4.w = (vx1 & vy1) ? w11 : 0.f;

        int4 i4;
        i4.x = (st + yc0 * sh + xc0) * HIDDEN;
        i4.y = (st + yc0 * sh + xc1) * HIDDEN;
        i4.z = (st + yc1 * sh + xc0) * HIDDEN;
        i4.w = (st + yc1 * sh + xc1) * HIDDEN;

        g_sw[(size_t)t * 16 + s] = w4;
        g_si[(size_t)t * 16 + s] = i4;
    }
}

// ================= personality: sampler (2 heads per warp, half2 channels) =================
__device__ void sample_body(int w2)
{
    int lane = threadIdx.x & 31;
    int hp = lane >> 4;
    int ch2 = lane & 15;

    int t = w2 * 2 + hp;
    int h = t & (HNUM - 1);
    int b = t / (NQ * HNUM);

    const __half* base = g_img_p + (size_t)b * ITOT * HIDDEN + h * CHD + ch2 * 2;
    const float4* wp = g_sw + (size_t)t * 16;
    const int4*   ip = g_si + (size_t)t * 16;

    float2 acc = make_float2(0.f, 0.f);
    #pragma unroll
    for (int s = 0; s < 16; s++) {
        float4 wt = __ldg(wp + s);
        int4   ix = __ldg(ip + s);
        float2 v0 = __half22float2(*(const __half2*)(base + ix.x));
        float2 v1 = __half22float2(*(const __half2*)(base + ix.y));
        float2 v2 = __half22float2(*(const __half2*)(base + ix.z));
        float2 v3 = __half22float2(*(const __half2*)(base + ix.w));
        acc.x += wt.x * v0.x + wt.y * v1.x + wt.z * v2.x + wt.w * v3.x;
        acc.y += wt.x * v0.y + wt.y * v1.y + wt.z * v2.y + wt.w * v3.y;
    }
    *(float2*)(g_hidden + (size_t)t * CHD + ch2 * 2) = acc;
}

// ================= mega-kernel: segment dispatch + dependency counters =================
// segment layout (block index ranges), topological order of the dependency DAG:
#define SEG_G1_LEN   340      // per batch: 170 m-tiles x 2 n-tiles
#define SEG_G2_LEN   384      // 64 m-tiles x 6 n-tiles
#define SEG_PREP_LEN 256      // 65536 / 256
#define SEG_SMP_LEN  512      // per batch: 4096 pairs / 8 warps
#define SEG_G3_LEN   256      // 64 m-tiles x 4 n-tiles
#define TOTAL_BLK    7712

struct MegaArgs {
    const float* img; const float* queries; const float* refpts;
    const float* b_img; const float* b_q; const float* b_out;
    float* out;
};

__global__ __launch_bounds__(256, 2) void mega(MegaArgs a)
{
    extern __shared__ char dynsm[];
    const int bx = blockIdx.x;

    // --- resolve segment ---
    // order: G1b0 | G2 | G1b1 | PREP | G1b2 | S0 | G1b3 | S1 | G1b4 | S2 |
    //        G1b5 | S3 | G1b6 | S4 | G1b7 | S5 | S6 | S7 | G3
    int x = bx;
    if (x < SEG_G1_LEN) {                                    // GEMM1 batch 0
        const float* Ar = a.img + ((size_t)0 * ITOT + (x >> 1) * 128) * GK;
        __half* Cr = g_img_p + ((size_t)0 * ITOT + (x >> 1) * 128) * HIDDEN;
        gemm1_tile(Ar, g_Wt1, a.b_img, Cr, (x & 1) * 128, dynsm);
        signal_ctr(0);
        return;
    }
    x -= SEG_G1_LEN;
    if (x < SEG_G2_LEN) {                                    // GEMM2
        hgemm_tile(a.queries, g_Wt2, a.b_q, g_qp, QPW, (x / 6) * 128, (x % 6) * 64, dynsm);
        signal_ctr(CTR_G2);
        return;
    }
    x -= SEG_G2_LEN;
    if (x < SEG_G1_LEN) {                                    // GEMM1 batch 1
        const float* Ar = a.img + ((size_t)1 * ITOT + (x >> 1) * 128) * GK;
        __half* Cr = g_img_p + ((size_t)1 * ITOT + (x >> 1) * 128) * HIDDEN;
        gemm1_tile(Ar, g_Wt1, a.b_img, Cr, (x & 1) * 128, dynsm);
        signal_ctr(1);
        return;
    }
    x -= SEG_G1_LEN;
    if (x < SEG_PREP_LEN) {                                  // prep (needs GEMM2)
        wait2(CTR_G2, SEG_G2_LEN, -1, 0);
        prep_body(x * 256 + threadIdx.x, g_qp, a.refpts);
        signal_ctr(CTR_PREP);
        return;
    }
    x -= SEG_PREP_LEN;
    #pragma unroll 1
    for (int b = 2; b <= 7; b++) {                           // G1b{2..7} | S{0..5}
        if (x < SEG_G1_LEN) {
            const float* Ar = a.img + ((size_t)b * ITOT + (x >> 1) * 128) * GK;
            __half* Cr = g_img_p + ((size_t)b * ITOT + (x >> 1) * 128) * HIDDEN;
            gemm1_tile(Ar, g_Wt1, a.b_img, Cr, (x & 1) * 128, dynsm);
            signal_ctr(b);
            return;
        }
        x -= SEG_G1_LEN;
        if (x < SEG_SMP_LEN) {
            int sb = b - 2;                                  // sampler batch
            wait2(sb, SEG_G1_LEN, CTR_PREP, SEG_PREP_LEN);
            sample_body(sb * 4096 + x * 8 + (threadIdx.x >> 5));
            signal_ctr(CTR_SMP);
            return;
        }
        x -= SEG_SMP_LEN;
    }
    if (x < 2 * SEG_SMP_LEN) {                               // samplers batches 6,7
        int sb = 6 + x / SEG_SMP_LEN;
        int lx = x % SEG_SMP_LEN;
        wait2(sb, SEG_G1_LEN, CTR_PREP, SEG_PREP_LEN);
        sample_body(sb * 4096 + lx * 8 + (threadIdx.x >> 5));
        signal_ctr(CTR_SMP);
        return;
    }
    x -= 2 * SEG_SMP_LEN;
    {                                                        // GEMM3 (needs all samplers)
        wait2(CTR_SMP, 8 * SEG_SMP_LEN, -1, 0);
        hgemm_tile(g_hidden, g_Wt3, a.b_out, a.out, HIDDEN, (x / 4) * 128, (x % 4) * 64, dynsm);
    }
}

// ---------------- small setup kernels ----------------
__global__ void zero_ctr() { if (threadIdx.x < 12) g_ctr[threadIdx.x] = 0; }

// W [K=256, N] fp32 row-major  ->  Wt [N, K] fp16 row-major
__global__ void pack_wt(const float* __restrict__ W, __half* __restrict__ Wt, int N) {
    __shared__ float t[32][33];
    int bx = blockIdx.x * 32;
    int by = blockIdx.y * 32;
    int x = threadIdx.x, y = threadIdx.y;
    #pragma unroll
    for (int i = 0; i < 32; i += 8)
        t[y + i][x] = W[(size_t)(by + y + i) * N + bx + x];
    __syncthreads();
    #pragma unroll
    for (int i = 0; i < 32; i += 8)
        Wt[(size_t)(bx + y + i) * GK + by + x] = __float2half_rn(t[x][y + i]);
}

// ---------------- launch ----------------
#define DYN_SMEM 40960   // max(gemm1 36864, hgemm 39936), 1KB-aligned

extern "C" void kernel_launch(void* const* d_in, const int* in_sizes, int n_in,
                              void* d_out, int out_size)
{
    MegaArgs a;
    a.img     = (const float*)d_in[0];
    a.queries = (const float*)d_in[2];
    a.refpts  = (const float*)d_in[3];
    const float* W_img = (const float*)d_in[4];
    a.b_img   = (const float*)d_in[5];
    const float* W_q   = (const float*)d_in[6];
    a.b_q     = (const float*)d_in[7];
    const float* W_out = (const float*)d_in[8];
    a.b_out   = (const float*)d_in[9];
    a.out     = (float*)d_out;

    __half *Wt1, *Wt2, *Wt3;
    cudaGetSymbolAddress((void**)&Wt1, g_Wt1);
    cudaGetSymbolAddress((void**)&Wt2, g_Wt2);
    cudaGetSymbolAddress((void**)&Wt3, g_Wt3);

    cudaFuncSetAttribute(mega, cudaFuncAttributeMaxDynamicSharedMemorySize, DYN_SMEM);

    zero_ctr<<<1, 32>>>();
    {
        dim3 blk(32, 8);
        pack_wt<<<dim3(HIDDEN / 32, GK / 32), blk>>>(W_img, Wt1, HIDDEN);
        pack_wt<<<dim3(QPW    / 32, GK / 32), blk>>>(W_q,   Wt2, QPW);
        pack_wt<<<dim3(EMBD   / 32, GK / 32), blk>>>(W_out, Wt3, EMBD);
    }
    mega<<<TOTAL_BLK, 256, DYN_SMEM>>>(a);
}

// round 10
// speedup vs baseline: 1.3902x; 1.1334x over previous
#include <cuda_runtime.h>
#include <cuda_fp16.h>
#include <cstdint>

// ---------------- problem constants ----------------
#define EMBD   256
#define HIDDEN 256
#define HNUM   8
#define CHD    32
#define BATCH  8
#define NQ     1024
#define ITOT   21760
#define QPW    384
#define GK     256
#define BNH    (BATCH * NQ * HNUM)   // 65536

// ---------------- scratch ----------------
__device__ __half  g_img_p[BATCH * ITOT * HIDDEN];
__device__ __half  g_Wt1[HIDDEN * GK];
__device__ __half  g_Wt2[QPW * GK];
__device__ __half  g_Wt3[EMBD * GK];
__device__ float   g_qp[BATCH * NQ * QPW];
__device__ float4  g_sw[BNH * 16];
__device__ int4    g_si[BNH * 16];
__device__ float   g_hidden[BATCH * NQ * HIDDEN];

__constant__ int c_sh[4]    = {128, 64, 32, 16};
__constant__ int c_start[4] = {0, 16384, 20480, 21504};

// ---------------- helpers ----------------
__device__ __forceinline__ void cp16(uint32_t dst, const void* src) {
    asm volatile("cp.async.cg.shared.global [%0], [%1], 16;" :: "r"(dst), "l"(src));
}
__device__ __forceinline__ uint32_t smem_u32(const void* p) {
    uint32_t a;
    asm("{ .reg .u64 t; cvta.to.shared.u64 t, %1; cvt.u32.u64 %0, t; }" : "=r"(a) : "l"(p));
    return a;
}
__device__ __forceinline__ uint32_t pack_h2(float lo, float hi) {
    uint32_t r;
    asm("cvt.rn.f16x2.f32 %0, %1, %2;" : "=r"(r) : "f"(hi), "f"(lo));
    return r;
}

// ================= GEMM1 tile (fp16 MMA, f32 acc, ldmatrix), C fp16 =================
#define APITCH  24
#define STG_H   (128 * APITCH)
#define NST     3
#define NKT16   (GK / 16)

__device__ void gemm1_tile(const float* __restrict__ Arows, const __half* __restrict__ Wt,
                           const float* __restrict__ bias, __half* __restrict__ Crows,
                           int n0, char* dynsm)
{
    __half* sA16 = (__half*)dynsm;
    __half* sB16 = sA16 + NST * STG_H;

    const int tid = threadIdx.x;
    const int wid = tid >> 5;
    const int lane = tid & 31;
    const int g = lane >> 2;
    const int tig = lane & 3;
    const int wm = (wid & 1) * 64;
    const int wn = (wid >> 1) * 32;

    const uint32_t lds_a_off = (uint32_t)((wm + (lane & 15)) * APITCH + (lane >> 4) * 8) * 2;

    uint32_t sbA[NST], sbB[NST];
    #pragma unroll
    for (int s = 0; s < NST; s++) {
        sbA[s] = smem_u32(sA16 + s * STG_H);
        sbB[s] = smem_u32(sB16 + s * STG_H);
    }

    const int arow = tid >> 1, aseg = tid & 1;
    const float* Ab = Arows + (size_t)arow * GK + aseg * 8;
    const __half* Bb = Wt + (size_t)(n0 + arow) * GK + aseg * 8;
    const uint32_t st_off = (uint32_t)(arow * APITCH + aseg * 8) * 2;

    float4 rA[2][2];
    auto ldgA = [&](int kt, int slot) {
        const float* p = Ab + kt * 16;
        rA[slot][0] = *(const float4*)p;
        rA[slot][1] = *(const float4*)(p + 4);
    };
    auto stsA = [&](int buf, int slot) {
        uint4 v;
        v.x = pack_h2(rA[slot][0].x, rA[slot][0].y);
        v.y = pack_h2(rA[slot][0].z, rA[slot][0].w);
        v.z = pack_h2(rA[slot][1].x, rA[slot][1].y);
        v.w = pack_h2(rA[slot][1].z, rA[slot][1].w);
        *(uint4*)((char*)(sA16 + buf * STG_H) + st_off) = v;
    };
    auto cpB = [&](int buf, int kt) {
        cp16(sbB[buf] + st_off, Bb + kt * 16);
    };

    float acc[4][4][4];
    #pragma unroll
    for (int i = 0; i < 4; i++)
        #pragma unroll
        for (int j = 0; j < 4; j++)
            #pragma unroll
            for (int r = 0; r < 4; r++) acc[i][j][r] = 0.f;

    ldgA(0, 0); ldgA(1, 1);
    cpB(0, 0);  asm volatile("cp.async.commit_group;" ::: "memory");
    cpB(1, 1);  asm volatile("cp.async.commit_group;" ::: "memory");
    stsA(0, 0); ldgA(2, 0);

    int buf = 0;
    #pragma unroll 1
    for (int kt = 0; kt < NKT16; kt++) {
        if (kt < NKT16 - 1) {
            asm volatile("cp.async.wait_group 1;" ::: "memory");
        } else {
            asm volatile("cp.async.wait_group 0;" ::: "memory");
        }
        __syncthreads();

        if (kt + 2 < NKT16) {
            int nb = buf + 2; if (nb >= NST) nb -= NST;
            cpB(nb, kt + 2);
            asm volatile("cp.async.commit_group;" ::: "memory");
        }

        uint32_t a[4][4], b[4][2];
        #pragma unroll
        for (int mf = 0; mf < 4; mf++) {
            uint32_t addr = sbA[buf] + lds_a_off + (uint32_t)(mf * 16 * APITCH) * 2;
            asm volatile(
                "ldmatrix.sync.aligned.m8n8.x4.shared.b16 {%0,%1,%2,%3}, [%4];"
                : "=r"(a[mf][0]), "=r"(a[mf][1]), "=r"(a[mf][2]), "=r"(a[mf][3])
                : "r"(addr));
        }
        const __half* Bs = sB16 + buf * STG_H;
        #pragma unroll
        for (int nf = 0; nf < 4; nf++) {
            int rb = wn + nf * 8 + g;
            b[nf][0] = *(const uint32_t*)&Bs[rb * APITCH + tig * 2];
            b[nf][1] = *(const uint32_t*)&Bs[rb * APITCH + tig * 2 + 8];
        }
        #pragma unroll
        for (int mf = 0; mf < 4; mf++)
            #pragma unroll
            for (int nf = 0; nf < 4; nf++) {
                asm volatile(
                    "mma.sync.aligned.m16n8k16.row.col.f32.f16.f16.f32 "
                    "{%0,%1,%2,%3}, {%4,%5,%6,%7}, {%8,%9}, {%0,%1,%2,%3};"
                    : "+f"(acc[mf][nf][0]), "+f"(acc[mf][nf][1]),
                      "+f"(acc[mf][nf][2]), "+f"(acc[mf][nf][3])
                    : "r"(a[mf][0]), "r"(a[mf][1]), "r"(a[mf][2]), "r"(a[mf][3]),
                      "r"(b[nf][0]), "r"(b[nf][1]));
            }

        if (kt + 1 < NKT16) {
            int nb = buf + 1; if (nb >= NST) nb -= NST;
            stsA(nb, (kt + 1) & 1);
        }
        if (kt + 3 < NKT16) ldgA(kt + 3, (kt + 3) & 1);

        if (++buf == NST) buf = 0;
    }

    #pragma unroll
    for (int nf = 0; nf < 4; nf++) {
        const int col = n0 + wn + nf * 8 + tig * 2;
        const float2 bb = *(const float2*)(bias + col);
        #pragma unroll
        for (int mf = 0; mf < 4; mf++) {
            const int row = wm + mf * 16 + g;
            uint32_t h0 = pack_h2(acc[mf][nf][0] + bb.x, acc[mf][nf][1] + bb.y);
            uint32_t h1 = pack_h2(acc[mf][nf][2] + bb.x, acc[mf][nf][3] + bb.y);
            *(uint32_t*)(Crows + (size_t)row * HIDDEN + col) = h0;
            *(uint32_t*)(Crows + (size_t)(row + 8) * HIDDEN + col) = h1;
        }
    }
}

// ================= fp32-out fp16 MMA GEMM tile (GEMM2 / GEMM3) =================
#define ROWPAD  20
#define BPITCH  24
#define A_STG   (128 * ROWPAD)
#define B_STG   (64 * BPITCH)
#define NSTAGE  3
#define NKT     (GK / 16)

__device__ void hgemm_tile(const float* __restrict__ A, const __half* __restrict__ Wt,
                           const float* __restrict__ bias, float* __restrict__ C,
                           int N, int m0, int n0, char* dynsm)
{
    float*  sA = (float*)dynsm;
    __half* sB = (__half*)(dynsm + NSTAGE * A_STG * 4);

    const int tid = threadIdx.x;
    const int wid = tid >> 5;
    const int lane = tid & 31;
    const int g = lane >> 2;
    const int tig = lane & 3;
    const int wm = (wid & 3) * 32;
    const int wn = (wid >> 2) * 32;

    float acc[2][4][4];
    #pragma unroll
    for (int i = 0; i < 2; i++)
        #pragma unroll
        for (int j = 0; j < 4; j++)
            #pragma unroll
            for (int r = 0; r < 4; r++) acc[i][j][r] = 0.f;

    uint32_t sbA[NSTAGE], sbB[NSTAGE];
    #pragma unroll
    for (int s = 0; s < NSTAGE; s++) {
        sbA[s] = smem_u32(sA + s * A_STG);
        sbB[s] = smem_u32(sB + s * B_STG);
    }

    auto load_stage = [&](int s, int kt) {
        #pragma unroll
        for (int i = 0; i < 2; i++) {
            int id = tid + i * 256;
            int row = id >> 2, c = id & 3;
            cp16(sbA[s] + (uint32_t)(row * ROWPAD + c * 4) * 4,
                 A + (size_t)(m0 + row) * GK + kt * 16 + c * 4);
        }
        if (tid < 128) {
            int row = tid >> 1, c = tid & 1;
            cp16(sbB[s] + (uint32_t)(row * BPITCH + c * 8) * 2,
                 Wt + (size_t)(n0 + row) * GK + kt * 16 + c * 8);
        }
    };

    load_stage(0, 0);
    asm volatile("cp.async.commit_group;" ::: "memory");
    load_stage(1, 1);
    asm volatile("cp.async.commit_group;" ::: "memory");

    #pragma unroll 1
    for (int kt = 0; kt < NKT; kt++) {
        if (kt < NKT - 1) {
            asm volatile("cp.async.wait_group 1;" ::: "memory");
        } else {
            asm volatile("cp.async.wait_group 0;" ::: "memory");
        }
        __syncthreads();

        if (kt + 2 < NKT) {
            load_stage((kt + 2) % NSTAGE, kt + 2);
            asm volatile("cp.async.commit_group;" ::: "memory");
        }

        const float*  As = sA + (kt % NSTAGE) * A_STG;
        const __half* Bs = sB + (kt % NSTAGE) * B_STG;

        uint32_t a[2][4], b[4][2];
        #pragma unroll
        for (int mf = 0; mf < 2; mf++) {
            int r = wm + mf * 16 + g;
            a[mf][0] = pack_h2(As[r * ROWPAD + tig * 2], As[r * ROWPAD + tig * 2 + 1]);
            a[mf][1] = pack_h2(As[(r + 8) * ROWPAD + tig * 2], As[(r + 8) * ROWPAD + tig * 2 + 1]);
            a[mf][2] = pack_h2(As[r * ROWPAD + tig * 2 + 8], As[r * ROWPAD + tig * 2 + 9]);
            a[mf][3] = pack_h2(As[(r + 8) * ROWPAD + tig * 2 + 8], As[(r + 8) * ROWPAD + tig * 2 + 9]);
        }
        #pragma unroll
        for (int nf = 0; nf < 4; nf++) {
            int rb = wn + nf * 8 + g;
            b[nf][0] = *(const uint32_t*)&Bs[rb * BPITCH + tig * 2];
            b[nf][1] = *(const uint32_t*)&Bs[rb * BPITCH + tig * 2 + 8];
        }
        #pragma unroll
        for (int mf = 0; mf < 2; mf++)
            #pragma unroll
            for (int nf = 0; nf < 4; nf++) {
                asm volatile(
                    "mma.sync.aligned.m16n8k16.row.col.f32.f16.f16.f32 "
                    "{%0,%1,%2,%3}, {%4,%5,%6,%7}, {%8,%9}, {%0,%1,%2,%3};"
                    : "+f"(acc[mf][nf][0]), "+f"(acc[mf][nf][1]),
                      "+f"(acc[mf][nf][2]), "+f"(acc[mf][nf][3])
                    : "r"(a[mf][0]), "r"(a[mf][1]), "r"(a[mf][2]), "r"(a[mf][3]),
                      "r"(b[nf][0]), "r"(b[nf][1]));
            }
    }

    #pragma unroll
    for (int nf = 0; nf < 4; nf++) {
        const int col = n0 + wn + nf * 8 + tig * 2;
        const float2 bb = *(const float2*)(bias + col);
        #pragma unroll
        for (int mf = 0; mf < 2; mf++) {
            const int row = m0 + wm + mf * 16 + g;
            float2 v0 = make_float2(acc[mf][nf][0] + bb.x, acc[mf][nf][1] + bb.y);
            float2 v1 = make_float2(acc[mf][nf][2] + bb.x, acc[mf][nf][3] + bb.y);
            *(float2*)(C + (size_t)row * N + col) = v0;
            *(float2*)(C + (size_t)(row + 8) * N + col) = v1;
        }
    }
}

// ================= launch A: GEMM2 segment + GEMM1 segment (independent) =================
__global__ __launch_bounds__(256, 2) void gemm_a(
    const float* __restrict__ img, const float* __restrict__ queries,
    const float* __restrict__ b_img, const float* __restrict__ b_q)
{
    extern __shared__ char dynsm[];
    int x = blockIdx.x;
    if (x < 384) {                       // GEMM2: [8192,256]@[256,384]
        hgemm_tile(queries, g_Wt2, b_q, g_qp, QPW, (x / 6) * 128, (x % 6) * 64, dynsm);
        return;
    }
    x -= 384;                            // GEMM1: 1360 slabs x 2 n-tiles
    const float* Ar = img + (size_t)(x >> 1) * 128 * GK;
    __half* Cr = g_img_p + (size_t)(x >> 1) * 128 * HIDDEN;
    gemm1_tile(Ar, g_Wt1, b_img, Cr, (x & 1) * 128, dynsm);
}

// ================= GEMM3 wrapper =================
__global__ __launch_bounds__(256, 2) void gemm3(const float* __restrict__ b_out,
                                                float* __restrict__ out)
{
    extern __shared__ char dynsm[];
    int x = blockIdx.x;                  // 64 m-tiles x 4 n-tiles
    hgemm_tile(g_hidden, g_Wt3, b_out, out, HIDDEN, (x >> 2) * 128, (x & 3) * 64, dynsm);
}

// ================= fused weight pack: three transposes in one launch =================
__device__ void pack_body(const float* __restrict__ W, __half* __restrict__ Wt,
                          int N, int bx, int by)
{
    __shared__ float t[32][33];
    int x = threadIdx.x, y = threadIdx.y;
    #pragma unroll
    for (int i = 0; i < 32; i += 8)
        t[y + i][x] = W[(size_t)(by + y + i) * N + bx + x];
    __syncthreads();
    #pragma unroll
    for (int i = 0; i < 32; i += 8)
        Wt[(size_t)(bx + y + i) * GK + by + x] = __float2half_rn(t[x][y + i]);
}

__global__ void pack_all(const float* __restrict__ W1, const float* __restrict__ W2,
                         const float* __restrict__ W3)
{
    int x = blockIdx.x;
    if (x < 64)        pack_body(W1, g_Wt1, HIDDEN, (x & 7) * 32, (x >> 3) * 32);
    else if (x < 160)  { x -= 64;  pack_body(W2, g_Wt2, QPW, (x % 12) * 32, (x / 12) * 32); }
    else               { x -= 160; pack_body(W3, g_Wt3, EMBD, (x & 7) * 32, (x >> 3) * 32); }
}

// ================= prep: softmax + weights/indices =================
__global__ void msda_prep(const float* __restrict__ qp,
                          const float* __restrict__ refpts)
{
    int t = blockIdx.x * blockDim.x + threadIdx.x;
    if (t >= BNH) return;
    int bn = t / HNUM;
    const float* q = qp + (size_t)t * 48;

    float lg[16];
    float mx = -1e30f;
    #pragma unroll
    for (int s = 0; s < 16; s++) { lg[s] = q[s * 3 + 2]; mx = fmaxf(mx, lg[s]); }
    float sum = 0.f;
    #pragma unroll
    for (int s = 0; s < 16; s++) { lg[s] = expf(lg[s] - mx); sum += lg[s]; }
    float inv = 1.0f / sum;

    float rx = refpts[bn * 2 + 0];
    float ry = refpts[bn * 2 + 1];

    #pragma unroll
    for (int s = 0; s < 16; s++) {
        int l = s >> 2;
        int sh = c_sh[l];
        float fs = (float)sh;
        int st = c_start[l];
        float aw = lg[s] * inv;

        float px = rx + q[s * 3 + 0] / fs;
        float py = ry + q[s * 3 + 1] / fs;
        float x = px * fs - 0.5f;
        float y = py * fs - 0.5f;
        float x0f = floorf(x), y0f = floorf(y);
        int x0 = (int)x0f, y0 = (int)y0f;
        float wx = x - x0f, wy = y - y0f;

        float w00 = (1.f - wx) * (1.f - wy) * aw;
        float w10 = wx * (1.f - wy) * aw;
        float w01 = (1.f - wx) * wy * aw;
        float w11 = wx * wy * aw;

        bool vx0 = (x0 >= 0) & (x0 < sh);
        bool vx1 = (x0 + 1 >= 0) & (x0 + 1 < sh);
        bool vy0 = (y0 >= 0) & (y0 < sh);
        bool vy1 = (y0 + 1 >= 0) & (y0 + 1 < sh);

        int xc0 = min(max(x0, 0), sh - 1);
        int xc1 = min(max(x0 + 1, 0), sh - 1);
        int yc0 = min(max(y0, 0), sh - 1);
        int yc1 = min(max(y0 + 1, 0), sh - 1);

        float4 w4;
        w4.x = (vx0 & vy0) ? w00 : 0.f;
        w4.y = (vx1 & vy0) ? w10 : 0.f;
        w4.z = (vx0 & vy1) ? w01 : 0.f;
        w4.w = (vx1 & vy1) ? w11 : 0.f;

        int4 i4;
        i4.x = (st + yc0 * sh + xc0) * HIDDEN;
        i4.y = (st + yc0 * sh + xc1) * HIDDEN;
        i4.z = (st + yc1 * sh + xc0) * HIDDEN;
        i4.w = (st + yc1 * sh + xc1) * HIDDEN;

        g_sw[(size_t)t * 16 + s] = w4;
        g_si[(size_t)t * 16 + s] = i4;
    }
}

// ================= sampler v3: one warp per head, 8 corners per LDG.128 =================
// lane = cg*4 + seg: cg = corner-slot (covers 2 samples x 4 corners per iteration),
// seg = 16B channel segment (8 channels). Per-lane fp32 accumulation, shfl-reduce over cg.
__global__ __launch_bounds__(256) void msda_sample3(
    const __half* __restrict__ img_p, float* __restrict__ out)
{
    const int t = blockIdx.x * 8 + (threadIdx.x >> 5);   // head id [0, BNH)
    const int lane = threadIdx.x & 31;
    const int cg = lane >> 2;
    const int seg = lane & 3;

    const int h = t & (HNUM - 1);
    const int b = t / (NQ * HNUM);
    const __half* base = img_p + (size_t)b * ITOT * HIDDEN + h * CHD + seg * 8;

    const int*   ip = (const int*)g_si + (size_t)t * 64;
    const float* wp = (const float*)g_sw + (size_t)t * 64;

    float acc[8];
    #pragma unroll
    for (int j = 0; j < 8; j++) acc[j] = 0.f;

    #pragma unroll
    for (int it = 0; it < 8; it++) {
        const int e = it * 8 + cg;
        const int idx = __ldg(ip + e);
        const float w = __ldg(wp + e);
        const uint4 v = *(const uint4*)(base + idx);
        const __half2* hv = (const __half2*)&v;
        #pragma unroll
        for (int j = 0; j < 4; j++) {
            float2 f = __half22float2(hv[j]);
            acc[2 * j]     += w * f.x;
            acc[2 * j + 1] += w * f.y;
        }
    }

    // reduce across the 8 corner-slots (lane xor 4, 8, 16)
    #pragma unroll
    for (int j = 0; j < 8; j++) {
        acc[j] += __shfl_xor_sync(0xffffffff, acc[j], 4);
        acc[j] += __shfl_xor_sync(0xffffffff, acc[j], 8);
        acc[j] += __shfl_xor_sync(0xffffffff, acc[j], 16);
    }

    if (cg == 0) {
        float* orow = out + (size_t)t * CHD + seg * 8;
        *(float4*)(orow)     = make_float4(acc[0], acc[1], acc[2], acc[3]);
        *(float4*)(orow + 4) = make_float4(acc[4], acc[5], acc[6], acc[7]);
    }
}

// ---------------- launch ----------------
#define DYN_SMEM 40960   // max(gemm1 36864, hgemm 39936)

extern "C" void kernel_launch(void* const* d_in, const int* in_sizes, int n_in,
                              void* d_out, int out_size)
{
    const float* img     = (const float*)d_in[0];
    const float* queries = (const float*)d_in[2];
    const float* refpts  = (const float*)d_in[3];
    const float* W_img   = (const float*)d_in[4];
    const float* b_img   = (const float*)d_in[5];
    const float* W_q     = (const float*)d_in[6];
    const float* b_q     = (const float*)d_in[7];
    const float* W_out   = (const float*)d_in[8];
    const float* b_out   = (const float*)d_in[9];
    float* out = (float*)d_out;

    float* qp;
    __half* img_p;
    cudaGetSymbolAddress((void**)&img_p, g_img_p);
    cudaGetSymbolAddress((void**)&qp,    g_qp);
    float* hidden;
    cudaGetSymbolAddress((void**)&hidden, g_hidden);

    cudaFuncSetAttribute(gemm_a, cudaFuncAttributeMaxDynamicSharedMemorySize, DYN_SMEM);
    cudaFuncSetAttribute(gemm3,  cudaFuncAttributeMaxDynamicSharedMemorySize, DYN_SMEM);

    // 0) pack all three weights (one launch)
    pack_all<<<224, dim3(32, 8)>>>(W_img, W_q, W_out);
    // 1) GEMM2 + GEMM1 merged (independent segments, one launch)
    gemm_a<<<384 + 2720, 256, DYN_SMEM>>>(img, queries, b_img, b_q);
    // 2) prep (softmax + weights/indices)
    msda_prep<<<BNH / 256, 256>>>(qp, refpts);
    // 3) sampler v3
    msda_sample3<<<BNH / 8, 256>>>(img_p, hidden);
    // 4) output projection
    gemm3<<<256, 256, DYN_SMEM>>>(b_out, out);
}